// round 4
// baseline (speedup 1.0000x reference)
#include <cuda_runtime.h>
#include <cstdint>

#define BSZ 16
#define SDIM 1024
#define EDIM 1024
#define HDIM 2048
#define MSALL (BSZ * SDIM)

// ---------------- scratch (device globals; no allocations) ----------------
__device__ float g_plr[(size_t)MSALL * EDIM];   // rounded pl
__device__ float g_samr[(size_t)MSALL * EDIM];  // rounded sam, later x_r
__device__ float g_q[(size_t)MSALL * EDIM];     // q (rounded), later attn (fp32)
__device__ float g_k[(size_t)MSALL * EDIM];     // k (rounded), later x (fp32)
__device__ float g_v[(size_t)MSALL * EDIM];     // ff output (fp32)
__device__ float g_vT[(size_t)MSALL * EDIM];    // v^T per batch (rounded)
__device__ float g_w[(size_t)BSZ * SDIM * SDIM];// scores -> rounded softmax weights
__device__ float g_h[(size_t)MSALL * HDIM];     // FFN hidden (rounded)
__device__ float g_WqT[EDIM * EDIM];
__device__ float g_WkT[EDIM * EDIM];
__device__ float g_WvT[EDIM * EDIM];
__device__ float g_W1T[EDIM * HDIM];
__device__ float g_W2T[EDIM * HDIM];
__device__ float g_part[BSZ * 64];
__device__ float g_bmax[BSZ];
__device__ float g_binv[BSZ];

__device__ __forceinline__ float rna(float v) {
    uint32_t u;
    asm("cvt.rna.tf32.f32 %0, %1;" : "=r"(u) : "f"(v));
    return __uint_as_float(u);
}

// ---------------- warp-MMA tf32 GEMM (mma.sync, sm80-style multistage) ----
// C[M,N] = alpha * A[M,K] @ B[N,K]^T. A,B fp32 (tf32-rounded), K-major.
// CTA 128x128, BK=16, 4 stages, 128 threads, 4 warps (2x2) of 64x64.
#define BMDIM 128
#define BKDIM 16
#define NSTAGE 4
#define APAD_STRIDE 20                         // floats per row (16 + 4 pad)
#define TILE_BYTES (BMDIM * APAD_STRIDE * 4)   // 10240
#define STAGE_BYTES (2 * TILE_BYTES)           // 20480
#define GEMM_SMEM (NSTAGE * STAGE_BYTES)       // 81920

__device__ __forceinline__ void cp_async16(uint32_t dst, const float* src) {
    size_t ga = __cvta_generic_to_global(src);
    asm volatile("cp.async.cg.shared.global [%0], [%1], 16;"
                 :: "r"(dst), "l"(ga) : "memory");
}

__device__ __forceinline__ void mma_tf32(float* c, const uint32_t* a, const uint32_t* b) {
    asm volatile(
        "mma.sync.aligned.m16n8k8.row.col.f32.tf32.tf32.f32 "
        "{%0,%1,%2,%3}, {%4,%5,%6,%7}, {%8,%9}, {%0,%1,%2,%3};"
        : "+f"(c[0]), "+f"(c[1]), "+f"(c[2]), "+f"(c[3])
        : "r"(a[0]), "r"(a[1]), "r"(a[2]), "r"(a[3]), "r"(b[0]), "r"(b[1]));
}

__device__ __forceinline__ uint32_t s2u(const void* p) {
    uint32_t a;
    asm("{ .reg .u64 t; cvta.to.shared.u64 t, %1; cvt.u32.u64 %0, t; }"
        : "=r"(a) : "l"(p));
    return a;
}

template <bool ROUND>
__global__ __launch_bounds__(128, 2)
void gemm_tc(const float* __restrict__ A, const float* __restrict__ B,
             float* __restrict__ C, int N, int K,
             long long sA, long long sB, long long sC,
             float alpha, const float* __restrict__ alphaPtr)
{
    extern __shared__ char smem[];
    const uint32_t sb = s2u(smem);
    const int tid = threadIdx.x;
    const int bz = blockIdx.z;
    A += (long long)bz * sA;
    B += (long long)bz * sB;
    C += (long long)bz * sC;
    const int m0 = blockIdx.y * BMDIM;
    const int n0 = blockIdx.x * BMDIM;
    const int nk = K / BKDIM;

    const int warp = tid >> 5, lane = tid & 31;
    const int wm = (warp & 1) * 64;   // warp m offset
    const int wn = (warp >> 1) * 64;  // warp n offset
    const int lg = lane >> 2;         // group id (0-7)
    const int lt = lane & 3;          // thread in group

    const int lrow = tid >> 2;
    const int lch = tid & 3;

    float acc[4][8][4];
#pragma unroll
    for (int i = 0; i < 4; i++)
#pragma unroll
        for (int j = 0; j < 8; j++)
#pragma unroll
            for (int c = 0; c < 4; c++) acc[i][j][c] = 0.f;

    // -------- prologue: fill stages 0..NSTAGE-2 --------
#pragma unroll
    for (int j = 0; j < NSTAGE - 1; j++) {
        uint32_t st = sb + j * STAGE_BYTES;
        int kt = j * BKDIM;
#pragma unroll
        for (int i = 0; i < 4; i++) {
            int row = lrow + i * 32;
            cp_async16(st + row * (APAD_STRIDE * 4) + lch * 16,
                       A + (long long)(m0 + row) * K + kt + lch * 4);
            cp_async16(st + TILE_BYTES + row * (APAD_STRIDE * 4) + lch * 16,
                       B + (long long)(n0 + row) * K + kt + lch * 4);
        }
        asm volatile("cp.async.commit_group;" ::: "memory");
    }

    for (int i = 0; i < nk; i++) {
        const int s = i % NSTAGE;
        const int rem = nk - 1 - i;
        if (rem >= 2)
            asm volatile("cp.async.wait_group 2;" ::: "memory");
        else if (rem == 1)
            asm volatile("cp.async.wait_group 1;" ::: "memory");
        else
            asm volatile("cp.async.wait_group 0;" ::: "memory");
        __syncthreads();   // single barrier per iter: orders stage reuse

        // prefetch stage i+NSTAGE-1 into the slot computed last iteration
        int jn = i + NSTAGE - 1;
        if (jn < nk) {
            uint32_t st = sb + (jn % NSTAGE) * STAGE_BYTES;
            int kt = jn * BKDIM;
#pragma unroll
            for (int u = 0; u < 4; u++) {
                int row = lrow + u * 32;
                cp_async16(st + row * (APAD_STRIDE * 4) + lch * 16,
                           A + (long long)(m0 + row) * K + kt + lch * 4);
                cp_async16(st + TILE_BYTES + row * (APAD_STRIDE * 4) + lch * 16,
                           B + (long long)(n0 + row) * K + kt + lch * 4);
            }
            asm volatile("cp.async.commit_group;" ::: "memory");
        }

        // -------- compute stage s: hoist ALL frag loads, then all MMAs ----
        const float* As = (const float*)(smem + s * STAGE_BYTES);
        const float* Bs = (const float*)(smem + s * STAGE_BYTES + TILE_BYTES);
        const float* ap0 = As + (wm + lg) * APAD_STRIDE + lt;
        const float* bp0 = Bs + (wn + lg) * APAD_STRIDE + lt;

        uint32_t af[2][4][4], bf[2][8][2];
#pragma unroll
        for (int ks = 0; ks < 2; ks++) {
#pragma unroll
            for (int mf = 0; mf < 4; mf++) {
                const float* p = ap0 + ks * 8 + mf * (16 * APAD_STRIDE);
                af[ks][mf][0] = __float_as_uint(p[0]);
                af[ks][mf][1] = __float_as_uint(p[8 * APAD_STRIDE]);
                af[ks][mf][2] = __float_as_uint(p[4]);
                af[ks][mf][3] = __float_as_uint(p[8 * APAD_STRIDE + 4]);
            }
#pragma unroll
            for (int nf = 0; nf < 8; nf++) {
                const float* p = bp0 + ks * 8 + nf * (8 * APAD_STRIDE);
                bf[ks][nf][0] = __float_as_uint(p[0]);
                bf[ks][nf][1] = __float_as_uint(p[4]);
            }
        }
#pragma unroll
        for (int ks = 0; ks < 2; ks++)
#pragma unroll
            for (int mf = 0; mf < 4; mf++)
#pragma unroll
                for (int nf = 0; nf < 8; nf++)
                    mma_tf32(acc[mf][nf], af[ks][mf], bf[ks][nf]);
    }

    // -------- epilogue --------
    const float aeff = alpha * (alphaPtr ? alphaPtr[bz] : 1.f);
#pragma unroll
    for (int mf = 0; mf < 4; mf++) {
        int r0 = m0 + wm + mf * 16 + lg;
#pragma unroll
        for (int nf = 0; nf < 8; nf++) {
            int cc = n0 + wn + nf * 8 + 2 * lt;
            float2 v0, v1;
            v0.x = acc[mf][nf][0] * aeff;
            v0.y = acc[mf][nf][1] * aeff;
            v1.x = acc[mf][nf][2] * aeff;
            v1.y = acc[mf][nf][3] * aeff;
            if (ROUND) {
                v0.x = rna(v0.x); v0.y = rna(v0.y);
                v1.x = rna(v1.x); v1.y = rna(v1.y);
            }
            *(float2*)&C[(long long)r0 * N + cc] = v0;
            *(float2*)&C[(long long)(r0 + 8) * N + cc] = v1;
        }
    }
}

// ---------------- elementwise round-copy ----------------
__global__ __launch_bounds__(256)
void round_copy_kernel(const float* __restrict__ s, float* __restrict__ d, int n4)
{
    int i = blockIdx.x * 256 + threadIdx.x;
    if (i < n4) {
        float4 v = ((const float4*)s)[i];
        v.x = rna(v.x); v.y = rna(v.y); v.z = rna(v.z); v.w = rna(v.w);
        ((float4*)d)[i] = v;
    }
}

// ---------------- transpose + round (weights only) ----------------
__global__ void transpose_round_kernel(const float* __restrict__ src,
                                       float* __restrict__ dst,
                                       int rows, int cols,
                                       long long sS, long long sD)
{
    __shared__ float tile[32][33];
    src += (long long)blockIdx.z * sS;
    dst += (long long)blockIdx.z * sD;
    int c0 = blockIdx.x * 32, r0 = blockIdx.y * 32;
    int x = threadIdx.x, y = threadIdx.y;
#pragma unroll
    for (int i = 0; i < 32; i += 8)
        tile[y + i][x] = src[(long long)(r0 + y + i) * cols + c0 + x];
    __syncthreads();
#pragma unroll
    for (int i = 0; i < 32; i += 8)
        dst[(long long)(c0 + y + i) * rows + r0 + x] = rna(tile[x][y + i]);
}

// ---------------- softmax over flattened S*S per batch ----------------
__global__ __launch_bounds__(256)
void max_part_kernel(const float* __restrict__ w, float* __restrict__ part)
{
    const int b = blockIdx.y;
    const float4* p = (const float4*)(w + (size_t)b * SDIM * SDIM)
                      + (size_t)blockIdx.x * 4096;
    float m = -3.4e38f;
    for (int i = threadIdx.x; i < 4096; i += 256) {
        float4 v = p[i];
        m = fmaxf(m, fmaxf(fmaxf(v.x, v.y), fmaxf(v.z, v.w)));
    }
    __shared__ float sh[256];
    sh[threadIdx.x] = m;
    __syncthreads();
    for (int o = 128; o > 0; o >>= 1) {
        if (threadIdx.x < o)
            sh[threadIdx.x] = fmaxf(sh[threadIdx.x], sh[threadIdx.x + o]);
        __syncthreads();
    }
    if (threadIdx.x == 0) part[b * 64 + blockIdx.x] = sh[0];
}

__global__ void fin_max_kernel(const float* __restrict__ part, float* __restrict__ bmax)
{
    const int b = blockIdx.x;
    __shared__ float sh[64];
    sh[threadIdx.x] = part[b * 64 + threadIdx.x];
    __syncthreads();
    for (int o = 32; o > 0; o >>= 1) {
        if (threadIdx.x < o)
            sh[threadIdx.x] = fmaxf(sh[threadIdx.x], sh[threadIdx.x + o]);
        __syncthreads();
    }
    if (threadIdx.x == 0) bmax[b] = sh[0];
}

__global__ __launch_bounds__(256)
void expsum_kernel(float* __restrict__ w, const float* __restrict__ bmax,
                   float* __restrict__ part)
{
    const int b = blockIdx.y;
    const float m = bmax[b];
    float4* p = (float4*)(w + (size_t)b * SDIM * SDIM) + (size_t)blockIdx.x * 4096;
    float s = 0.f;
    for (int i = threadIdx.x; i < 4096; i += 256) {
        float4 v = p[i];
        v.x = rna(__expf(v.x - m));
        v.y = rna(__expf(v.y - m));
        v.z = rna(__expf(v.z - m));
        v.w = rna(__expf(v.w - m));
        s += (v.x + v.y) + (v.z + v.w);
        p[i] = v;
    }
    __shared__ float sh[256];
    sh[threadIdx.x] = s;
    __syncthreads();
    for (int o = 128; o > 0; o >>= 1) {
        if (threadIdx.x < o) sh[threadIdx.x] += sh[threadIdx.x + o];
        __syncthreads();
    }
    if (threadIdx.x == 0) part[b * 64 + blockIdx.x] = sh[0];
}

__global__ void fin_sum_kernel(const float* __restrict__ part, float* __restrict__ binv)
{
    const int b = blockIdx.x;
    __shared__ float sh[64];
    sh[threadIdx.x] = part[b * 64 + threadIdx.x];
    __syncthreads();
    for (int o = 32; o > 0; o >>= 1) {
        if (threadIdx.x < o) sh[threadIdx.x] += sh[threadIdx.x + o];
        __syncthreads();
    }
    if (threadIdx.x == 0) binv[b] = 1.f / sh[0];
}

// ---------------- fused residual-add + LayerNorm (+optional tf32 copy) ----
__global__ __launch_bounds__(256)
void add_ln_kernel(const float* __restrict__ a, const float* __restrict__ res,
                   const float* __restrict__ gam, const float* __restrict__ bet,
                   float* __restrict__ out, float* __restrict__ out_r)
{
    const int row = blockIdx.x;
    const int t = threadIdx.x;
    const float4 va = ((const float4*)(a + (size_t)row * EDIM))[t];
    const float4 vr = ((const float4*)(res + (size_t)row * EDIM))[t];
    float x0 = va.x + vr.x, x1 = va.y + vr.y, x2 = va.z + vr.z, x3 = va.w + vr.w;

    __shared__ float sh[256];
    sh[t] = (x0 + x1) + (x2 + x3);
    __syncthreads();
    for (int o = 128; o > 0; o >>= 1) {
        if (t < o) sh[t] += sh[t + o];
        __syncthreads();
    }
    const float mean = sh[0] * (1.f / EDIM);
    __syncthreads();

    const float d0 = x0 - mean, d1 = x1 - mean, d2 = x2 - mean, d3 = x3 - mean;
    sh[t] = (d0 * d0 + d1 * d1) + (d2 * d2 + d3 * d3);
    __syncthreads();
    for (int o = 128; o > 0; o >>= 1) {
        if (t < o) sh[t] += sh[t + o];
        __syncthreads();
    }
    const float rstd = rsqrtf(sh[0] * (1.f / EDIM) + 1e-5f);

    const float4 vg = ((const float4*)gam)[t];
    const float4 vb = ((const float4*)bet)[t];
    float4 o4;
    o4.x = d0 * rstd * vg.x + vb.x;
    o4.y = d1 * rstd * vg.y + vb.y;
    o4.z = d2 * rstd * vg.z + vb.z;
    o4.w = d3 * rstd * vg.w + vb.w;
    ((float4*)(out + (size_t)row * EDIM))[t] = o4;
    if (out_r) {
        float4 r4;
        r4.x = rna(o4.x); r4.y = rna(o4.y); r4.z = rna(o4.z); r4.w = rna(o4.w);
        ((float4*)(out_r + (size_t)row * EDIM))[t] = r4;
    }
}

// ---------------- launch ----------------
extern "C" void kernel_launch(void* const* d_in, const int* in_sizes, int n_in,
                              void* d_out, int out_size)
{
    const float* pl   = (const float*)d_in[0];
    const float* sam  = (const float*)d_in[1];
    const float* Wq   = (const float*)d_in[2];
    const float* Wk   = (const float*)d_in[3];
    const float* Wv   = (const float*)d_in[4];
    const float* ln1g = (const float*)d_in[5];
    const float* ln1b = (const float*)d_in[6];
    const float* W1   = (const float*)d_in[7];
    const float* W2   = (const float*)d_in[8];
    const float* ln2g = (const float*)d_in[9];
    const float* ln2b = (const float*)d_in[10];
    float* out = (float*)d_out;

    float *plr, *samr, *q, *k, *v, *vT, *w, *h;
    float *WqT, *WkT, *WvT, *W1T, *W2T, *part, *bmax, *binv;
    cudaGetSymbolAddress((void**)&plr, g_plr);
    cudaGetSymbolAddress((void**)&samr, g_samr);
    cudaGetSymbolAddress((void**)&q, g_q);
    cudaGetSymbolAddress((void**)&k, g_k);
    cudaGetSymbolAddress((void**)&v, g_v);
    cudaGetSymbolAddress((void**)&vT, g_vT);
    cudaGetSymbolAddress((void**)&w, g_w);
    cudaGetSymbolAddress((void**)&h, g_h);
    cudaGetSymbolAddress((void**)&WqT, g_WqT);
    cudaGetSymbolAddress((void**)&WkT, g_WkT);
    cudaGetSymbolAddress((void**)&WvT, g_WvT);
    cudaGetSymbolAddress((void**)&W1T, g_W1T);
    cudaGetSymbolAddress((void**)&W2T, g_W2T);
    cudaGetSymbolAddress((void**)&part, g_part);
    cudaGetSymbolAddress((void**)&bmax, g_bmax);
    cudaGetSymbolAddress((void**)&binv, g_binv);

    cudaFuncSetAttribute(gemm_tc<false>, cudaFuncAttributeMaxDynamicSharedMemorySize, GEMM_SMEM);
    cudaFuncSetAttribute(gemm_tc<true>,  cudaFuncAttributeMaxDynamicSharedMemorySize, GEMM_SMEM);

    const long long sSE = (long long)SDIM * EDIM;
    const long long sSS = (long long)SDIM * SDIM;

    // round inputs to tf32
    round_copy_kernel<<<(MSALL * EDIM / 4 + 255) / 256, 256>>>(pl, plr, MSALL * EDIM / 4);
    round_copy_kernel<<<(MSALL * EDIM / 4 + 255) / 256, 256>>>(sam, samr, MSALL * EDIM / 4);

    // transpose + round weights: W^T is [N,K] K-major
    transpose_round_kernel<<<dim3(32, 32, 1), dim3(32, 8)>>>(Wq, WqT, EDIM, EDIM, 0, 0);
    transpose_round_kernel<<<dim3(32, 32, 1), dim3(32, 8)>>>(Wk, WkT, EDIM, EDIM, 0, 0);
    transpose_round_kernel<<<dim3(32, 32, 1), dim3(32, 8)>>>(Wv, WvT, EDIM, EDIM, 0, 0);
    transpose_round_kernel<<<dim3(64, 32, 1), dim3(32, 8)>>>(W1, W1T, EDIM, HDIM, 0, 0);
    transpose_round_kernel<<<dim3(32, 64, 1), dim3(32, 8)>>>(W2, W2T, HDIM, EDIM, 0, 0);

    // q = pl @ Wq (rounded), k = sam @ Wk (rounded)
    gemm_tc<true><<<dim3(EDIM / 128, MSALL / 128, 1), 128, GEMM_SMEM>>>(
        plr, WqT, q, EDIM, EDIM, 0, 0, 0, 1.f, nullptr);
    gemm_tc<true><<<dim3(EDIM / 128, MSALL / 128, 1), 128, GEMM_SMEM>>>(
        samr, WkT, k, EDIM, EDIM, 0, 0, 0, 1.f, nullptr);

    // vT_b = WvT @ sam_b^T  (direct transposed V, rounded): C[E,S] per batch
    gemm_tc<true><<<dim3(SDIM / 128, EDIM / 128, BSZ), 128, GEMM_SMEM>>>(
        WvT, samr, vT, SDIM, EDIM, 0, sSE, sSE, 1.f, nullptr);

    // scores = (q @ k^T) / 32 per batch
    gemm_tc<false><<<dim3(SDIM / 128, SDIM / 128, BSZ), 128, GEMM_SMEM>>>(
        q, k, w, SDIM, EDIM, sSE, sSE, sSS, 0.03125f, nullptr);

    // flattened softmax per batch (stores tf32-rounded weights)
    max_part_kernel<<<dim3(64, BSZ), 256>>>(w, part);
    fin_max_kernel<<<BSZ, 64>>>(part, bmax);
    expsum_kernel<<<dim3(64, BSZ), 256>>>(w, bmax, part);
    fin_sum_kernel<<<BSZ, 64>>>(part, binv);

    // attn = (w @ vT^T) * binv  -> into q (fp32)
    gemm_tc<false><<<dim3(EDIM / 128, SDIM / 128, BSZ), 128, GEMM_SMEM>>>(
        w, vT, q, EDIM, SDIM, sSS, sSE, sSE, 1.f, binv);

    // x = LN(attn + pl): fp32 into k, rounded into samr
    add_ln_kernel<<<MSALL, 256>>>(q, pl, ln1g, ln1b, k, samr);

    // h = x @ W1 (rounded); ff = h @ W2 (fp32 into v)
    gemm_tc<true><<<dim3(HDIM / 128, MSALL / 128, 1), 128, GEMM_SMEM>>>(
        samr, W1T, h, HDIM, EDIM, 0, 0, 0, 1.f, nullptr);
    gemm_tc<false><<<dim3(EDIM / 128, MSALL / 128, 1), 128, GEMM_SMEM>>>(
        h, W2T, v, EDIM, HDIM, 0, 0, 0, 1.f, nullptr);

    // out = LN(ff + x)
    add_ln_kernel<<<MSALL, 256>>>(v, k, ln2g, ln2b, out, nullptr);
}

// round 5
// speedup vs baseline: 1.7968x; 1.7968x over previous
#include <cuda_runtime.h>
#include <cuda_fp16.h>
#include <cstdint>

#define BSZ 16
#define SDIM 1024
#define EDIM 1024
#define HDIM 2048
#define MSALL (BSZ * SDIM)

// ---------------- scratch (device globals; no allocations) ----------------
__device__ __half g_plh[(size_t)MSALL * EDIM];    // pl (half)
__device__ __half g_samh[(size_t)MSALL * EDIM];   // sam (half), later x (half)
__device__ __half g_qh[(size_t)MSALL * EDIM];     // q (half)
__device__ __half g_kh[(size_t)MSALL * EDIM];     // k (half)
__device__ __half g_vTh[(size_t)MSALL * EDIM];    // v^T per batch (half)
__device__ __half g_wh[(size_t)BSZ * SDIM * SDIM];// softmax weights (half)
__device__ __half g_hh[(size_t)MSALL * HDIM];     // FFN hidden (half)
__device__ __half g_WqTh[EDIM * EDIM];
__device__ __half g_WkTh[EDIM * EDIM];
__device__ __half g_WvTh[EDIM * EDIM];
__device__ __half g_W1Th[EDIM * HDIM];
__device__ __half g_W2Th[EDIM * HDIM];
__device__ float g_w[(size_t)BSZ * SDIM * SDIM];  // fp32 scores
__device__ float g_f1[(size_t)MSALL * EDIM];      // attn, later ff (fp32)
__device__ float g_f2[(size_t)MSALL * EDIM];      // x (fp32)
__device__ float g_part[BSZ * 64];
__device__ float g_bmax[BSZ];
__device__ float g_binv[BSZ];

// ---------------- fp16 warp-MMA GEMM (m16n8k16, multistage cp.async) -----
// C[M,N] = alpha * A[M,K] @ B[N,K]^T. A,B half, K-major. C fp32 or half.
// CTA 128x128, BK=32, 4 stages, 128 threads, 4 warps (2x2) of 64x64.
#define BMDIM 128
#define BKH 32                                  // halves per k-iter
#define NSTAGE 4
#define HPAD 40                                 // halves per row (32 + 8 pad)
#define TILE_BYTES (BMDIM * HPAD * 2)           // 10240
#define STAGE_BYTES (2 * TILE_BYTES)            // 20480
#define GEMM_SMEM (NSTAGE * STAGE_BYTES)        // 81920

__device__ __forceinline__ void cp_async16(uint32_t dst, const void* src) {
    size_t ga = __cvta_generic_to_global(src);
    asm volatile("cp.async.cg.shared.global [%0], [%1], 16;"
                 :: "r"(dst), "l"(ga) : "memory");
}

__device__ __forceinline__ void mma_f16(float* c, const uint32_t* a, const uint32_t* b) {
    asm volatile(
        "mma.sync.aligned.m16n8k16.row.col.f32.f16.f16.f32 "
        "{%0,%1,%2,%3}, {%4,%5,%6,%7}, {%8,%9}, {%0,%1,%2,%3};"
        : "+f"(c[0]), "+f"(c[1]), "+f"(c[2]), "+f"(c[3])
        : "r"(a[0]), "r"(a[1]), "r"(a[2]), "r"(a[3]), "r"(b[0]), "r"(b[1]));
}

__device__ __forceinline__ uint32_t s2u(const void* p) {
    uint32_t a;
    asm("{ .reg .u64 t; cvta.to.shared.u64 t, %1; cvt.u32.u64 %0, t; }"
        : "=r"(a) : "l"(p));
    return a;
}

// load one 128x32-half tile (rows at stride HPAD) via cp.async
__device__ __forceinline__ void load_tile_h(const __half* base, int ldk, int r0,
                                            int kt, uint32_t st, int tid) {
#pragma unroll
    for (int i = 0; i < 4; i++) {
        int slot = tid + (i << 7);
        int row = slot >> 2;       // 0..127
        int ch = slot & 3;         // 16B chunk within 64B row
        cp_async16(st + row * (HPAD * 2) + ch * 16,
                   base + (size_t)(r0 + row) * ldk + kt + ch * 8);
    }
}

template <bool OUTH>
__global__ __launch_bounds__(128, 2)
void gemm_h(const __half* __restrict__ A, const __half* __restrict__ B,
            void* __restrict__ Cv, int N, int K,
            long long sA, long long sB, long long sC,
            float alpha, const float* __restrict__ alphaPtr)
{
    extern __shared__ char smem[];
    const uint32_t sb = s2u(smem);
    const int tid = threadIdx.x;
    const int bz = blockIdx.z;
    A += (long long)bz * sA;
    B += (long long)bz * sB;
    const int m0 = blockIdx.y * BMDIM;
    const int n0 = blockIdx.x * BMDIM;
    const int nk = K / BKH;

    const int warp = tid >> 5, lane = tid & 31;
    const int wm = (warp & 1) * 64;
    const int wn = (warp >> 1) * 64;
    const int lg = lane >> 2;
    const int lt = lane & 3;

    float acc[4][8][4];
#pragma unroll
    for (int i = 0; i < 4; i++)
#pragma unroll
        for (int j = 0; j < 8; j++)
#pragma unroll
            for (int c = 0; c < 4; c++) acc[i][j][c] = 0.f;

    // -------- prologue --------
#pragma unroll
    for (int j = 0; j < NSTAGE - 1; j++) {
        uint32_t st = sb + j * STAGE_BYTES;
        load_tile_h(A, K, m0, j * BKH, st, tid);
        load_tile_h(B, K, n0, j * BKH, st + TILE_BYTES, tid);
        asm volatile("cp.async.commit_group;" ::: "memory");
    }

    for (int i = 0; i < nk; i++) {
        const int s = i % NSTAGE;
        const int rem = nk - 1 - i;
        if (rem >= 2)
            asm volatile("cp.async.wait_group 2;" ::: "memory");
        else if (rem == 1)
            asm volatile("cp.async.wait_group 1;" ::: "memory");
        else
            asm volatile("cp.async.wait_group 0;" ::: "memory");
        __syncthreads();

        int jn = i + NSTAGE - 1;
        if (jn < nk) {
            uint32_t st = sb + (jn % NSTAGE) * STAGE_BYTES;
            load_tile_h(A, K, m0, jn * BKH, st, tid);
            load_tile_h(B, K, n0, jn * BKH, st + TILE_BYTES, tid);
            asm volatile("cp.async.commit_group;" ::: "memory");
        }

        const __half* As = (const __half*)(smem + s * STAGE_BYTES);
        const __half* Bs = (const __half*)(smem + s * STAGE_BYTES + TILE_BYTES);
        const __half* ap0 = As + (wm + lg) * HPAD + lt * 2;
        const __half* bp0 = Bs + (wn + lg) * HPAD + lt * 2;

#pragma unroll
        for (int ks = 0; ks < 2; ks++) {      // two k16 steps per BK=32
            uint32_t af[4][4], bf[8][2];
#pragma unroll
            for (int mf = 0; mf < 4; mf++) {
                const __half* p = ap0 + ks * 16 + mf * (16 * HPAD);
                af[mf][0] = *(const uint32_t*)(p);
                af[mf][1] = *(const uint32_t*)(p + 8 * HPAD);
                af[mf][2] = *(const uint32_t*)(p + 8);
                af[mf][3] = *(const uint32_t*)(p + 8 * HPAD + 8);
            }
#pragma unroll
            for (int nf = 0; nf < 8; nf++) {
                const __half* p = bp0 + ks * 16 + nf * (8 * HPAD);
                bf[nf][0] = *(const uint32_t*)(p);
                bf[nf][1] = *(const uint32_t*)(p + 8);
            }
#pragma unroll
            for (int mf = 0; mf < 4; mf++)
#pragma unroll
                for (int nf = 0; nf < 8; nf++)
                    mma_f16(acc[mf][nf], af[mf], bf[nf]);
        }
    }

    // -------- epilogue --------
    const float aeff = alpha * (alphaPtr ? alphaPtr[bz] : 1.f);
#pragma unroll
    for (int mf = 0; mf < 4; mf++) {
        int r0 = m0 + wm + mf * 16 + lg;
#pragma unroll
        for (int nf = 0; nf < 8; nf++) {
            int cc = n0 + wn + nf * 8 + 2 * lt;
            float v00 = acc[mf][nf][0] * aeff;
            float v01 = acc[mf][nf][1] * aeff;
            float v10 = acc[mf][nf][2] * aeff;
            float v11 = acc[mf][nf][3] * aeff;
            if (OUTH) {
                __half* C = (__half*)Cv + (long long)bz * sC;
                *(__half2*)&C[(long long)r0 * N + cc] = __floats2half2_rn(v00, v01);
                *(__half2*)&C[(long long)(r0 + 8) * N + cc] = __floats2half2_rn(v10, v11);
            } else {
                float* C = (float*)Cv + (long long)bz * sC;
                float2 a0; a0.x = v00; a0.y = v01;
                float2 a1; a1.x = v10; a1.y = v11;
                *(float2*)&C[(long long)r0 * N + cc] = a0;
                *(float2*)&C[(long long)(r0 + 8) * N + cc] = a1;
            }
        }
    }
}

// ---------------- fp32 -> fp16 copy ----------------
__global__ __launch_bounds__(256)
void tohalf_kernel(const float* __restrict__ s, __half2* __restrict__ d, int n4)
{
    int i = blockIdx.x * 256 + threadIdx.x;
    if (i < n4) {
        float4 v = ((const float4*)s)[i];
        d[2 * i] = __floats2half2_rn(v.x, v.y);
        d[2 * i + 1] = __floats2half2_rn(v.z, v.w);
    }
}

// ---------------- transpose fp32 -> fp16 ----------------
__global__ void transpose_h_kernel(const float* __restrict__ src,
                                   __half* __restrict__ dst,
                                   int rows, int cols)
{
    __shared__ float tile[32][33];
    int c0 = blockIdx.x * 32, r0 = blockIdx.y * 32;
    int x = threadIdx.x, y = threadIdx.y;
#pragma unroll
    for (int i = 0; i < 32; i += 8)
        tile[y + i][x] = src[(long long)(r0 + y + i) * cols + c0 + x];
    __syncthreads();
#pragma unroll
    for (int i = 0; i < 32; i += 8)
        dst[(long long)(c0 + y + i) * rows + r0 + x] = __float2half_rn(tile[x][y + i]);
}

// ---------------- softmax over flattened S*S per batch ----------------
__global__ __launch_bounds__(256)
void max_part_kernel(const float* __restrict__ w, float* __restrict__ part)
{
    const int b = blockIdx.y;
    const float4* p = (const float4*)(w + (size_t)b * SDIM * SDIM)
                      + (size_t)blockIdx.x * 4096;
    float m = -3.4e38f;
    for (int i = threadIdx.x; i < 4096; i += 256) {
        float4 v = p[i];
        m = fmaxf(m, fmaxf(fmaxf(v.x, v.y), fmaxf(v.z, v.w)));
    }
    __shared__ float sh[256];
    sh[threadIdx.x] = m;
    __syncthreads();
    for (int o = 128; o > 0; o >>= 1) {
        if (threadIdx.x < o)
            sh[threadIdx.x] = fmaxf(sh[threadIdx.x], sh[threadIdx.x + o]);
        __syncthreads();
    }
    if (threadIdx.x == 0) part[b * 64 + blockIdx.x] = sh[0];
}

__global__ void fin_max_kernel(const float* __restrict__ part, float* __restrict__ bmax)
{
    const int b = blockIdx.x;
    __shared__ float sh[64];
    sh[threadIdx.x] = part[b * 64 + threadIdx.x];
    __syncthreads();
    for (int o = 32; o > 0; o >>= 1) {
        if (threadIdx.x < o)
            sh[threadIdx.x] = fmaxf(sh[threadIdx.x], sh[threadIdx.x + o]);
        __syncthreads();
    }
    if (threadIdx.x == 0) bmax[b] = sh[0];
}

// exp, round to half (stored for the attn GEMM), and sum the rounded values
__global__ __launch_bounds__(256)
void expsum_kernel(const float* __restrict__ w, __half2* __restrict__ wh,
                   const float* __restrict__ bmax, float* __restrict__ part)
{
    const int b = blockIdx.y;
    const float m = bmax[b];
    const float4* p = (const float4*)(w + (size_t)b * SDIM * SDIM)
                      + (size_t)blockIdx.x * 4096;
    __half2* ph = wh + (size_t)b * (SDIM * SDIM / 2) + (size_t)blockIdx.x * 8192;
    float s = 0.f;
    for (int i = threadIdx.x; i < 4096; i += 256) {
        float4 v = p[i];
        __half2 h0 = __floats2half2_rn(__expf(v.x - m), __expf(v.y - m));
        __half2 h1 = __floats2half2_rn(__expf(v.z - m), __expf(v.w - m));
        ph[2 * i] = h0;
        ph[2 * i + 1] = h1;
        float2 f0 = __half22float2(h0), f1 = __half22float2(h1);
        s += (f0.x + f0.y) + (f1.x + f1.y);
    }
    __shared__ float sh[256];
    sh[threadIdx.x] = s;
    __syncthreads();
    for (int o = 128; o > 0; o >>= 1) {
        if (threadIdx.x < o) sh[threadIdx.x] += sh[threadIdx.x + o];
        __syncthreads();
    }
    if (threadIdx.x == 0) part[b * 64 + blockIdx.x] = sh[0];
}

__global__ void fin_sum_kernel(const float* __restrict__ part, float* __restrict__ binv)
{
    const int b = blockIdx.x;
    __shared__ float sh[64];
    sh[threadIdx.x] = part[b * 64 + threadIdx.x];
    __syncthreads();
    for (int o = 32; o > 0; o >>= 1) {
        if (threadIdx.x < o) sh[threadIdx.x] += sh[threadIdx.x + o];
        __syncthreads();
    }
    if (threadIdx.x == 0) binv[b] = 1.f / sh[0];
}

// ---------------- fused residual-add + LayerNorm (+optional half copy) ----
__global__ __launch_bounds__(256)
void add_ln_kernel(const float* __restrict__ a, const float* __restrict__ res,
                   const float* __restrict__ gam, const float* __restrict__ bet,
                   float* __restrict__ out, __half2* __restrict__ out_h)
{
    const int row = blockIdx.x;
    const int t = threadIdx.x;
    const float4 va = ((const float4*)(a + (size_t)row * EDIM))[t];
    const float4 vr = ((const float4*)(res + (size_t)row * EDIM))[t];
    float x0 = va.x + vr.x, x1 = va.y + vr.y, x2 = va.z + vr.z, x3 = va.w + vr.w;

    __shared__ float sh[256];
    sh[t] = (x0 + x1) + (x2 + x3);
    __syncthreads();
    for (int o = 128; o > 0; o >>= 1) {
        if (t < o) sh[t] += sh[t + o];
        __syncthreads();
    }
    const float mean = sh[0] * (1.f / EDIM);
    __syncthreads();

    const float d0 = x0 - mean, d1 = x1 - mean, d2 = x2 - mean, d3 = x3 - mean;
    sh[t] = (d0 * d0 + d1 * d1) + (d2 * d2 + d3 * d3);
    __syncthreads();
    for (int o = 128; o > 0; o >>= 1) {
        if (t < o) sh[t] += sh[t + o];
        __syncthreads();
    }
    const float rstd = rsqrtf(sh[0] * (1.f / EDIM) + 1e-5f);

    const float4 vg = ((const float4*)gam)[t];
    const float4 vb = ((const float4*)bet)[t];
    float4 o4;
    o4.x = d0 * rstd * vg.x + vb.x;
    o4.y = d1 * rstd * vg.y + vb.y;
    o4.z = d2 * rstd * vg.z + vb.z;
    o4.w = d3 * rstd * vg.w + vb.w;
    ((float4*)(out + (size_t)row * EDIM))[t] = o4;
    if (out_h) {
        out_h[(size_t)row * (EDIM / 2) + 2 * t] = __floats2half2_rn(o4.x, o4.y);
        out_h[(size_t)row * (EDIM / 2) + 2 * t + 1] = __floats2half2_rn(o4.z, o4.w);
    }
}

// ---------------- launch ----------------
extern "C" void kernel_launch(void* const* d_in, const int* in_sizes, int n_in,
                              void* d_out, int out_size)
{
    const float* pl   = (const float*)d_in[0];
    const float* sam  = (const float*)d_in[1];
    const float* Wq   = (const float*)d_in[2];
    const float* Wk   = (const float*)d_in[3];
    const float* Wv   = (const float*)d_in[4];
    const float* ln1g = (const float*)d_in[5];
    const float* ln1b = (const float*)d_in[6];
    const float* W1   = (const float*)d_in[7];
    const float* W2   = (const float*)d_in[8];
    const float* ln2g = (const float*)d_in[9];
    const float* ln2b = (const float*)d_in[10];
    float* out = (float*)d_out;

    __half *plh, *samh, *qh, *kh, *vTh, *wh, *hh;
    __half *WqTh, *WkTh, *WvTh, *W1Th, *W2Th;
    float *w, *f1, *f2, *part, *bmax, *binv;
    cudaGetSymbolAddress((void**)&plh, g_plh);
    cudaGetSymbolAddress((void**)&samh, g_samh);
    cudaGetSymbolAddress((void**)&qh, g_qh);
    cudaGetSymbolAddress((void**)&kh, g_kh);
    cudaGetSymbolAddress((void**)&vTh, g_vTh);
    cudaGetSymbolAddress((void**)&wh, g_wh);
    cudaGetSymbolAddress((void**)&hh, g_hh);
    cudaGetSymbolAddress((void**)&WqTh, g_WqTh);
    cudaGetSymbolAddress((void**)&WkTh, g_WkTh);
    cudaGetSymbolAddress((void**)&WvTh, g_WvTh);
    cudaGetSymbolAddress((void**)&W1Th, g_W1Th);
    cudaGetSymbolAddress((void**)&W2Th, g_W2Th);
    cudaGetSymbolAddress((void**)&w, g_w);
    cudaGetSymbolAddress((void**)&f1, g_f1);
    cudaGetSymbolAddress((void**)&f2, g_f2);
    cudaGetSymbolAddress((void**)&part, g_part);
    cudaGetSymbolAddress((void**)&bmax, g_bmax);
    cudaGetSymbolAddress((void**)&binv, g_binv);

    cudaFuncSetAttribute(gemm_h<false>, cudaFuncAttributeMaxDynamicSharedMemorySize, GEMM_SMEM);
    cudaFuncSetAttribute(gemm_h<true>,  cudaFuncAttributeMaxDynamicSharedMemorySize, GEMM_SMEM);

    const long long sSE = (long long)SDIM * EDIM;
    const long long sSS = (long long)SDIM * SDIM;

    // inputs -> half
    tohalf_kernel<<<(MSALL * EDIM / 4 + 255) / 256, 256>>>(pl, (__half2*)plh, MSALL * EDIM / 4);
    tohalf_kernel<<<(MSALL * EDIM / 4 + 255) / 256, 256>>>(sam, (__half2*)samh, MSALL * EDIM / 4);

    // weights -> transposed half ([N,K] K-major)
    transpose_h_kernel<<<dim3(32, 32), dim3(32, 8)>>>(Wq, WqTh, EDIM, EDIM);
    transpose_h_kernel<<<dim3(32, 32), dim3(32, 8)>>>(Wk, WkTh, EDIM, EDIM);
    transpose_h_kernel<<<dim3(32, 32), dim3(32, 8)>>>(Wv, WvTh, EDIM, EDIM);
    transpose_h_kernel<<<dim3(64, 32), dim3(32, 8)>>>(W1, W1Th, EDIM, HDIM);
    transpose_h_kernel<<<dim3(32, 64), dim3(32, 8)>>>(W2, W2Th, HDIM, EDIM);

    // q = pl @ Wq, k = sam @ Wk (half out)
    gemm_h<true><<<dim3(EDIM / 128, MSALL / 128, 1), 128, GEMM_SMEM>>>(
        plh, WqTh, qh, EDIM, EDIM, 0, 0, 0, 1.f, nullptr);
    gemm_h<true><<<dim3(EDIM / 128, MSALL / 128, 1), 128, GEMM_SMEM>>>(
        samh, WkTh, kh, EDIM, EDIM, 0, 0, 0, 1.f, nullptr);

    // vT_b = WvT @ sam_b^T (half out): C[E,S] per batch
    gemm_h<true><<<dim3(SDIM / 128, EDIM / 128, BSZ), 128, GEMM_SMEM>>>(
        WvTh, samh, vTh, SDIM, EDIM, 0, sSE, sSE, 1.f, nullptr);

    // scores = (q @ k^T) / 32 per batch (fp32 out)
    gemm_h<false><<<dim3(SDIM / 128, SDIM / 128, BSZ), 128, GEMM_SMEM>>>(
        qh, kh, w, SDIM, EDIM, sSE, sSE, sSS, 0.03125f, nullptr);

    // flattened softmax per batch -> half weights
    max_part_kernel<<<dim3(64, BSZ), 256>>>(w, part);
    fin_max_kernel<<<BSZ, 64>>>(part, bmax);
    expsum_kernel<<<dim3(64, BSZ), 256>>>(w, (__half2*)wh, bmax, part);
    fin_sum_kernel<<<BSZ, 64>>>(part, binv);

    // attn = (wh @ vT^T) * binv -> f1 (fp32)
    gemm_h<false><<<dim3(EDIM / 128, SDIM / 128, BSZ), 128, GEMM_SMEM>>>(
        wh, vTh, f1, EDIM, SDIM, sSS, sSE, sSE, 1.f, binv);

    // x = LN(attn + pl): fp32 -> f2, half -> samh (reused)
    add_ln_kernel<<<MSALL, 256>>>(f1, pl, ln1g, ln1b, f2, (__half2*)samh);

    // h = x @ W1 (half out); ff = h @ W2 (fp32 into f1)
    gemm_h<true><<<dim3(HDIM / 128, MSALL / 128, 1), 128, GEMM_SMEM>>>(
        samh, W1Th, hh, HDIM, EDIM, 0, 0, 0, 1.f, nullptr);
    gemm_h<false><<<dim3(EDIM / 128, MSALL / 128, 1), 128, GEMM_SMEM>>>(
        hh, W2Th, f1, EDIM, HDIM, 0, 0, 0, 1.f, nullptr);

    // out = LN(ff + x)
    add_ln_kernel<<<MSALL, 256>>>(f1, f2, ln2g, ln2b, out, nullptr);
}

// round 6
// speedup vs baseline: 2.0338x; 1.1319x over previous
#include <cuda_runtime.h>
#include <cuda_fp16.h>
#include <cstdint>

#define BSZ 16
#define SDIM 1024
#define EDIM 1024
#define HDIM 2048
#define MSALL (BSZ * SDIM)

// ---------------- scratch (device globals; no allocations) ----------------
__device__ __half g_plh[(size_t)MSALL * EDIM];    // pl (half)
__device__ __half g_samh[(size_t)MSALL * EDIM];   // sam (half), later x (half)
__device__ __half g_qh[(size_t)MSALL * EDIM];     // q (half)
__device__ __half g_kh[(size_t)MSALL * EDIM];     // k (half)
__device__ __half g_vTh[(size_t)MSALL * EDIM];    // v^T per batch (half)
__device__ __half g_wh[(size_t)BSZ * SDIM * SDIM];// softmax weights (half)
__device__ __half g_hh[(size_t)MSALL * HDIM];     // FFN hidden (half)
__device__ __half g_WqTh[EDIM * EDIM];
__device__ __half g_WkTh[EDIM * EDIM];
__device__ __half g_WvTh[EDIM * EDIM];
__device__ __half g_W1Th[EDIM * HDIM];
__device__ __half g_W2Th[EDIM * HDIM];
__device__ float g_w[(size_t)BSZ * SDIM * SDIM];  // fp32 scores
__device__ float g_f1[(size_t)MSALL * EDIM];      // attn, later ff (fp32)
__device__ float g_f2[(size_t)MSALL * EDIM];      // x (fp32)
__device__ float g_part[BSZ * 64];
__device__ unsigned g_bmax_enc[BSZ];              // order-preserving encoded max
__device__ float g_binv[BSZ];

// ---------------- fp16 warp-MMA GEMM (m16n8k16, ldmatrix, multistage) -----
// C[M,N] = alpha * A[M,K] @ B[N,K]^T. A,B half, K-major. C fp32 or half.
// CTA 128x128, BK=32, 4 stages, 128 threads, 4 warps (2x2) of 64x64.
#define BMDIM 128
#define BKH 32                                  // halves per k-iter
#define NSTAGE 4
#define HPAD 40                                 // halves per row (32 + 8 pad)
#define TILE_BYTES (BMDIM * HPAD * 2)           // 10240
#define STAGE_BYTES (2 * TILE_BYTES)            // 20480
#define GEMM_SMEM (NSTAGE * STAGE_BYTES)        // 81920

__device__ __forceinline__ void cp_async16(uint32_t dst, const void* src) {
    size_t ga = __cvta_generic_to_global(src);
    asm volatile("cp.async.cg.shared.global [%0], [%1], 16;"
                 :: "r"(dst), "l"(ga) : "memory");
}

__device__ __forceinline__ void mma_f16(float* c, const uint32_t* a, const uint32_t* b) {
    asm volatile(
        "mma.sync.aligned.m16n8k16.row.col.f32.f16.f16.f32 "
        "{%0,%1,%2,%3}, {%4,%5,%6,%7}, {%8,%9}, {%0,%1,%2,%3};"
        : "+f"(c[0]), "+f"(c[1]), "+f"(c[2]), "+f"(c[3])
        : "r"(a[0]), "r"(a[1]), "r"(a[2]), "r"(a[3]), "r"(b[0]), "r"(b[1]));
}

#define LDSM_X4(r0, r1, r2, r3, addr) \
    asm volatile("ldmatrix.sync.aligned.m8n8.x4.shared.b16 {%0,%1,%2,%3}, [%4];" \
                 : "=r"(r0), "=r"(r1), "=r"(r2), "=r"(r3) : "r"(addr))

__device__ __forceinline__ uint32_t s2u(const void* p) {
    uint32_t a;
    asm("{ .reg .u64 t; cvta.to.shared.u64 t, %1; cvt.u32.u64 %0, t; }"
        : "=r"(a) : "l"(p));
    return a;
}

// load one 128x32-half tile (rows at stride HPAD) via cp.async
__device__ __forceinline__ void load_tile_h(const __half* base, int ldk, int r0,
                                            int kt, uint32_t st, int tid) {
#pragma unroll
    for (int i = 0; i < 4; i++) {
        int slot = tid + (i << 7);
        int row = slot >> 2;       // 0..127
        int ch = slot & 3;         // 16B chunk within 64B row
        cp_async16(st + row * (HPAD * 2) + ch * 16,
                   base + (size_t)(r0 + row) * ldk + kt + ch * 8);
    }
}

template <bool OUTH>
__global__ __launch_bounds__(128, 2)
void gemm_h(const __half* __restrict__ A, const __half* __restrict__ B,
            void* __restrict__ Cv, int N, int K,
            long long sA, long long sB, long long sC,
            float alpha, const float* __restrict__ alphaPtr,
            unsigned* __restrict__ bmaxEnc)
{
    extern __shared__ char smem[];
    const uint32_t sb = s2u(smem);
    const int tid = threadIdx.x;
    const int bz = blockIdx.z;
    A += (long long)bz * sA;
    B += (long long)bz * sB;
    const int m0 = blockIdx.y * BMDIM;
    const int n0 = blockIdx.x * BMDIM;
    const int nk = K / BKH;

    const int warp = tid >> 5, lane = tid & 31;
    const int wm = (warp & 1) * 64;
    const int wn = (warp >> 1) * 64;
    const int lg = lane >> 2;
    const int lt = lane & 3;

    // ldmatrix per-lane byte offsets within a stage
    const uint32_t aoff = (wm + (lane & 15)) * (HPAD * 2) + (lane & 16);
    const uint32_t boff = (wn + (lane & 7) + ((lane & 16) >> 1)) * (HPAD * 2)
                          + ((lane & 8) << 1);

    float acc[4][8][4];
#pragma unroll
    for (int i = 0; i < 4; i++)
#pragma unroll
        for (int j = 0; j < 8; j++)
#pragma unroll
            for (int c = 0; c < 4; c++) acc[i][j][c] = 0.f;

    // -------- prologue --------
#pragma unroll
    for (int j = 0; j < NSTAGE - 1; j++) {
        uint32_t st = sb + j * STAGE_BYTES;
        load_tile_h(A, K, m0, j * BKH, st, tid);
        load_tile_h(B, K, n0, j * BKH, st + TILE_BYTES, tid);
        asm volatile("cp.async.commit_group;" ::: "memory");
    }

    for (int i = 0; i < nk; i++) {
        const int s = i % NSTAGE;
        const int rem = nk - 1 - i;
        if (rem >= 2)
            asm volatile("cp.async.wait_group 2;" ::: "memory");
        else if (rem == 1)
            asm volatile("cp.async.wait_group 1;" ::: "memory");
        else
            asm volatile("cp.async.wait_group 0;" ::: "memory");
        __syncthreads();

        int jn = i + NSTAGE - 1;
        if (jn < nk) {
            uint32_t st = sb + (jn % NSTAGE) * STAGE_BYTES;
            load_tile_h(A, K, m0, jn * BKH, st, tid);
            load_tile_h(B, K, n0, jn * BKH, st + TILE_BYTES, tid);
            asm volatile("cp.async.commit_group;" ::: "memory");
        }

        const uint32_t ab = sb + s * STAGE_BYTES + aoff;
        const uint32_t bb = sb + s * STAGE_BYTES + TILE_BYTES + boff;

#pragma unroll
        for (int ks = 0; ks < 2; ks++) {      // two k16 steps per BK=32
            uint32_t af[4][4], bf[8][2];
#pragma unroll
            for (int mf = 0; mf < 4; mf++)
                LDSM_X4(af[mf][0], af[mf][1], af[mf][2], af[mf][3],
                        ab + mf * (16 * HPAD * 2) + ks * 32);
#pragma unroll
            for (int np = 0; np < 4; np++)
                LDSM_X4(bf[2 * np][0], bf[2 * np][1],
                        bf[2 * np + 1][0], bf[2 * np + 1][1],
                        bb + np * (16 * HPAD * 2) + ks * 32);
#pragma unroll
            for (int mf = 0; mf < 4; mf++)
#pragma unroll
                for (int nf = 0; nf < 8; nf++)
                    mma_f16(acc[mf][nf], af[mf], bf[nf]);
        }
    }

    // -------- epilogue --------
    const float aeff = alpha * (alphaPtr ? alphaPtr[bz] : 1.f);
    float lmax = -3.4e38f;
#pragma unroll
    for (int mf = 0; mf < 4; mf++) {
        int r0 = m0 + wm + mf * 16 + lg;
#pragma unroll
        for (int nf = 0; nf < 8; nf++) {
            int cc = n0 + wn + nf * 8 + 2 * lt;
            float v00 = acc[mf][nf][0] * aeff;
            float v01 = acc[mf][nf][1] * aeff;
            float v10 = acc[mf][nf][2] * aeff;
            float v11 = acc[mf][nf][3] * aeff;
            if (bmaxEnc) {
                lmax = fmaxf(lmax, fmaxf(fmaxf(v00, v01), fmaxf(v10, v11)));
            }
            if (OUTH) {
                __half* C = (__half*)Cv + (long long)bz * sC;
                *(__half2*)&C[(long long)r0 * N + cc] = __floats2half2_rn(v00, v01);
                *(__half2*)&C[(long long)(r0 + 8) * N + cc] = __floats2half2_rn(v10, v11);
            } else {
                float* C = (float*)Cv + (long long)bz * sC;
                float2 a0; a0.x = v00; a0.y = v01;
                float2 a1; a1.x = v10; a1.y = v11;
                *(float2*)&C[(long long)r0 * N + cc] = a0;
                *(float2*)&C[(long long)(r0 + 8) * N + cc] = a1;
            }
        }
    }

    if (bmaxEnc) {
        __shared__ float red[4];
#pragma unroll
        for (int o = 16; o > 0; o >>= 1)
            lmax = fmaxf(lmax, __shfl_xor_sync(0xffffffffu, lmax, o));
        if (lane == 0) red[warp] = lmax;
        __syncthreads();
        if (tid == 0) {
            float m = fmaxf(fmaxf(red[0], red[1]), fmaxf(red[2], red[3]));
            unsigned u = __float_as_uint(m);
            unsigned enc = (u & 0x80000000u) ? ~u : (u | 0x80000000u);
            atomicMax(&bmaxEnc[bz], enc);
        }
    }
}

// ---------------- init encoded max ----------------
__global__ void init_bmax_kernel(unsigned* e) { e[threadIdx.x] = 0u; }

// ---------------- fp32 -> fp16 copy ----------------
__global__ __launch_bounds__(256)
void tohalf_kernel(const float* __restrict__ s, __half2* __restrict__ d, int n4)
{
    int i = blockIdx.x * 256 + threadIdx.x;
    if (i < n4) {
        float4 v = ((const float4*)s)[i];
        d[2 * i] = __floats2half2_rn(v.x, v.y);
        d[2 * i + 1] = __floats2half2_rn(v.z, v.w);
    }
}

// ---------------- transpose fp32 -> fp16 ----------------
__global__ void transpose_h_kernel(const float* __restrict__ src,
                                   __half* __restrict__ dst,
                                   int rows, int cols)
{
    __shared__ float tile[32][33];
    int c0 = blockIdx.x * 32, r0 = blockIdx.y * 32;
    int x = threadIdx.x, y = threadIdx.y;
#pragma unroll
    for (int i = 0; i < 32; i += 8)
        tile[y + i][x] = src[(long long)(r0 + y + i) * cols + c0 + x];
    __syncthreads();
#pragma unroll
    for (int i = 0; i < 32; i += 8)
        dst[(long long)(c0 + y + i) * rows + r0 + x] = __float2half_rn(tile[x][y + i]);
}

// ---------------- softmax: exp + half store + partial sums ----------------
__global__ __launch_bounds__(256)
void expsum_kernel(const float* __restrict__ w, __half2* __restrict__ wh,
                   const unsigned* __restrict__ bmaxEnc, float* __restrict__ part)
{
    const int b = blockIdx.y;
    const unsigned ue = bmaxEnc[b];
    const unsigned du = (ue & 0x80000000u) ? (ue ^ 0x80000000u) : ~ue;
    const float m = __uint_as_float(du);
    const float4* p = (const float4*)(w + (size_t)b * SDIM * SDIM)
                      + (size_t)blockIdx.x * 4096;
    __half2* ph = wh + (size_t)b * (SDIM * SDIM / 2) + (size_t)blockIdx.x * 8192;
    float s = 0.f;
    for (int i = threadIdx.x; i < 4096; i += 256) {
        float4 v = p[i];
        __half2 h0 = __floats2half2_rn(__expf(v.x - m), __expf(v.y - m));
        __half2 h1 = __floats2half2_rn(__expf(v.z - m), __expf(v.w - m));
        ph[2 * i] = h0;
        ph[2 * i + 1] = h1;
        float2 f0 = __half22float2(h0), f1 = __half22float2(h1);
        s += (f0.x + f0.y) + (f1.x + f1.y);
    }
    __shared__ float sh[256];
    sh[threadIdx.x] = s;
    __syncthreads();
    for (int o = 128; o > 0; o >>= 1) {
        if (threadIdx.x < o) sh[threadIdx.x] += sh[threadIdx.x + o];
        __syncthreads();
    }
    if (threadIdx.x == 0) part[b * 64 + blockIdx.x] = sh[0];
}

__global__ void fin_sum_kernel(const float* __restrict__ part, float* __restrict__ binv)
{
    const int b = blockIdx.x;
    __shared__ float sh[64];
    sh[threadIdx.x] = part[b * 64 + threadIdx.x];
    __syncthreads();
    for (int o = 32; o > 0; o >>= 1) {
        if (threadIdx.x < o) sh[threadIdx.x] += sh[threadIdx.x + o];
        __syncthreads();
    }
    if (threadIdx.x == 0) binv[b] = 1.f / sh[0];
}

// ---------------- fused residual-add + LayerNorm (+optional half copy) ----
__global__ __launch_bounds__(256)
void add_ln_kernel(const float* __restrict__ a, const float* __restrict__ res,
                   const float* __restrict__ gam, const float* __restrict__ bet,
                   float* __restrict__ out, __half2* __restrict__ out_h)
{
    const int row = blockIdx.x;
    const int t = threadIdx.x;
    const float4 va = ((const float4*)(a + (size_t)row * EDIM))[t];
    const float4 vr = ((const float4*)(res + (size_t)row * EDIM))[t];
    float x0 = va.x + vr.x, x1 = va.y + vr.y, x2 = va.z + vr.z, x3 = va.w + vr.w;

    __shared__ float sh[256];
    sh[t] = (x0 + x1) + (x2 + x3);
    __syncthreads();
    for (int o = 128; o > 0; o >>= 1) {
        if (t < o) sh[t] += sh[t + o];
        __syncthreads();
    }
    const float mean = sh[0] * (1.f / EDIM);
    __syncthreads();

    const float d0 = x0 - mean, d1 = x1 - mean, d2 = x2 - mean, d3 = x3 - mean;
    sh[t] = (d0 * d0 + d1 * d1) + (d2 * d2 + d3 * d3);
    __syncthreads();
    for (int o = 128; o > 0; o >>= 1) {
        if (t < o) sh[t] += sh[t + o];
        __syncthreads();
    }
    const float rstd = rsqrtf(sh[0] * (1.f / EDIM) + 1e-5f);

    const float4 vg = ((const float4*)gam)[t];
    const float4 vb = ((const float4*)bet)[t];
    float4 o4;
    o4.x = d0 * rstd * vg.x + vb.x;
    o4.y = d1 * rstd * vg.y + vb.y;
    o4.z = d2 * rstd * vg.z + vb.z;
    o4.w = d3 * rstd * vg.w + vb.w;
    ((float4*)(out + (size_t)row * EDIM))[t] = o4;
    if (out_h) {
        out_h[(size_t)row * (EDIM / 2) + 2 * t] = __floats2half2_rn(o4.x, o4.y);
        out_h[(size_t)row * (EDIM / 2) + 2 * t + 1] = __floats2half2_rn(o4.z, o4.w);
    }
}

// ---------------- launch ----------------
extern "C" void kernel_launch(void* const* d_in, const int* in_sizes, int n_in,
                              void* d_out, int out_size)
{
    const float* pl   = (const float*)d_in[0];
    const float* sam  = (const float*)d_in[1];
    const float* Wq   = (const float*)d_in[2];
    const float* Wk   = (const float*)d_in[3];
    const float* Wv   = (const float*)d_in[4];
    const float* ln1g = (const float*)d_in[5];
    const float* ln1b = (const float*)d_in[6];
    const float* W1   = (const float*)d_in[7];
    const float* W2   = (const float*)d_in[8];
    const float* ln2g = (const float*)d_in[9];
    const float* ln2b = (const float*)d_in[10];
    float* out = (float*)d_out;

    __half *plh, *samh, *qh, *kh, *vTh, *wh, *hh;
    __half *WqTh, *WkTh, *WvTh, *W1Th, *W2Th;
    float *w, *f1, *f2, *part, *binv;
    unsigned* bmaxe;
    cudaGetSymbolAddress((void**)&plh, g_plh);
    cudaGetSymbolAddress((void**)&samh, g_samh);
    cudaGetSymbolAddress((void**)&qh, g_qh);
    cudaGetSymbolAddress((void**)&kh, g_kh);
    cudaGetSymbolAddress((void**)&vTh, g_vTh);
    cudaGetSymbolAddress((void**)&wh, g_wh);
    cudaGetSymbolAddress((void**)&hh, g_hh);
    cudaGetSymbolAddress((void**)&WqTh, g_WqTh);
    cudaGetSymbolAddress((void**)&WkTh, g_WkTh);
    cudaGetSymbolAddress((void**)&WvTh, g_WvTh);
    cudaGetSymbolAddress((void**)&W1Th, g_W1Th);
    cudaGetSymbolAddress((void**)&W2Th, g_W2Th);
    cudaGetSymbolAddress((void**)&w, g_w);
    cudaGetSymbolAddress((void**)&f1, g_f1);
    cudaGetSymbolAddress((void**)&f2, g_f2);
    cudaGetSymbolAddress((void**)&part, g_part);
    cudaGetSymbolAddress((void**)&bmaxe, g_bmax_enc);
    cudaGetSymbolAddress((void**)&binv, g_binv);

    cudaFuncSetAttribute(gemm_h<false>, cudaFuncAttributeMaxDynamicSharedMemorySize, GEMM_SMEM);
    cudaFuncSetAttribute(gemm_h<true>,  cudaFuncAttributeMaxDynamicSharedMemorySize, GEMM_SMEM);

    const long long sSE = (long long)SDIM * EDIM;
    const long long sSS = (long long)SDIM * SDIM;

    // init encoded per-batch max
    init_bmax_kernel<<<1, BSZ>>>(bmaxe);

    // inputs -> half
    tohalf_kernel<<<(MSALL * EDIM / 4 + 255) / 256, 256>>>(pl, (__half2*)plh, MSALL * EDIM / 4);
    tohalf_kernel<<<(MSALL * EDIM / 4 + 255) / 256, 256>>>(sam, (__half2*)samh, MSALL * EDIM / 4);

    // weights -> transposed half ([N,K] K-major)
    transpose_h_kernel<<<dim3(32, 32), dim3(32, 8)>>>(Wq, WqTh, EDIM, EDIM);
    transpose_h_kernel<<<dim3(32, 32), dim3(32, 8)>>>(Wk, WkTh, EDIM, EDIM);
    transpose_h_kernel<<<dim3(32, 32), dim3(32, 8)>>>(Wv, WvTh, EDIM, EDIM);
    transpose_h_kernel<<<dim3(64, 32), dim3(32, 8)>>>(W1, W1Th, EDIM, HDIM);
    transpose_h_kernel<<<dim3(32, 64), dim3(32, 8)>>>(W2, W2Th, HDIM, EDIM);

    // q = pl @ Wq, k = sam @ Wk (half out)
    gemm_h<true><<<dim3(EDIM / 128, MSALL / 128, 1), 128, GEMM_SMEM>>>(
        plh, WqTh, qh, EDIM, EDIM, 0, 0, 0, 1.f, nullptr, nullptr);
    gemm_h<true><<<dim3(EDIM / 128, MSALL / 128, 1), 128, GEMM_SMEM>>>(
        samh, WkTh, kh, EDIM, EDIM, 0, 0, 0, 1.f, nullptr, nullptr);

    // vT_b = WvT @ sam_b^T (half out): C[E,S] per batch
    gemm_h<true><<<dim3(SDIM / 128, EDIM / 128, BSZ), 128, GEMM_SMEM>>>(
        WvTh, samh, vTh, SDIM, EDIM, 0, sSE, sSE, 1.f, nullptr, nullptr);

    // scores = (q @ k^T) / 32 per batch (fp32 out) + fused per-batch max
    gemm_h<false><<<dim3(SDIM / 128, SDIM / 128, BSZ), 128, GEMM_SMEM>>>(
        qh, kh, w, SDIM, EDIM, sSE, sSE, sSS, 0.03125f, nullptr, bmaxe);

    // flattened softmax per batch -> half weights
    expsum_kernel<<<dim3(64, BSZ), 256>>>(w, (__half2*)wh, bmaxe, part);
    fin_sum_kernel<<<BSZ, 64>>>(part, binv);

    // attn = (wh @ vT^T) * binv -> f1 (fp32)
    gemm_h<false><<<dim3(EDIM / 128, SDIM / 128, BSZ), 128, GEMM_SMEM>>>(
        wh, vTh, f1, EDIM, SDIM, sSS, sSE, sSE, 1.f, binv, nullptr);

    // x = LN(attn + pl): fp32 -> f2, half -> samh (reused)
    add_ln_kernel<<<MSALL, 256>>>(f1, pl, ln1g, ln1b, f2, (__half2*)samh);

    // h = x @ W1 (half out); ff = h @ W2 (fp32 into f1)
    gemm_h<true><<<dim3(HDIM / 128, MSALL / 128, 1), 128, GEMM_SMEM>>>(
        samh, W1Th, hh, HDIM, EDIM, 0, 0, 0, 1.f, nullptr, nullptr);
    gemm_h<false><<<dim3(EDIM / 128, MSALL / 128, 1), 128, GEMM_SMEM>>>(
        hh, W2Th, f1, EDIM, HDIM, 0, 0, 0, 1.f, nullptr, nullptr);

    // out = LN(ff + x)
    add_ln_kernel<<<MSALL, 256>>>(f1, f2, ln2g, ln2b, out, nullptr);
}